// round 3
// baseline (speedup 1.0000x reference)
#include <cuda_runtime.h>

#define X 256
#define Y 256
#define Z 192
#define YX (X*Y)
#define NB 2
#define TX 64          // tile width (elements); one warp row = 32 lanes x float2
#define TY 16          // output rows per tile
#define NW (TY + 4)    // 20 warps (y-halo 2 each side)
#define NTH (NW * 32)  // 640 threads
#define ZCHUNKS 2
#define ZCK (Z / ZCHUNKS)  // 96
#define RS 68          // smem row stride in floats: [1]=left edge, [2..65]=row, [66]=right edge

__device__ __forceinline__ float2 fmin2(float2 a, float2 b) {
    return make_float2(fminf(a.x, b.x), fminf(a.y, b.y));
}
__device__ __forceinline__ float2 fmax2(float2 a, float2 b) {
    return make_float2(fmaxf(a.x, b.x), fmaxf(a.y, b.y));
}

// out = relu(img - dilate3x3x3(erode3x3x3(img))), stride 1, pad 1.
// erode: min-pool, +inf padding. dilate: max-pool, -inf padding (domain mask).
// Warp = one y-row (incl. halo); lane = float2 x-column; z marched with
// register rings. x-window stages via warp shuffle; y-window stages via smem
// (2 ping-pong buffers, 2 barriers/plane). Tile x-halo lives in a register
// ring shared by lanes 0 (left) and 31 (right).
__global__ __launch_bounds__(NTH, 2)
void soft_skel_kernel(const float* __restrict__ img, float* __restrict__ out) {
    __shared__ float sA[NW * RS];
    __shared__ float sB[NW * RS];

    const int lane = threadIdx.x & 31;
    const int w    = threadIdx.x >> 5;
    const int bx0  = blockIdx.x * TX;
    const int by0  = blockIdx.y * TY;
    const int bz   = blockIdx.z;
    const int b    = bz / ZCHUNKS;
    const int z0   = (bz % ZCHUNKS) * ZCK;
    const int z1   = z0 + ZCK;

    const int  gx   = bx0 + lane * 2;
    const int  gy   = by0 + w - 2;
    const bool rowV = (gy >= 0) && (gy < Y);
    const bool isL  = (lane == 0);
    const bool isR  = (lane == 31);
    const bool isE  = isL || isR;
    const int  hx      = isR ? (bx0 + TX) : (bx0 - 2);    // halo float2 start
    const bool haloInX = (hx >= 0) && (hx + 1 < X);       // fully in or out
    const bool edgeInX = isR ? (bx0 + TX < X) : (bx0 >= 1); // erode pos at tile edge
    const int  ec   = isR ? 66 : 1;
    const bool doOut = (w >= 2) && (w < 2 + TY);

    float* rowA  = sA + w * RS;
    float* rowAU = sA + (w == 0 ? 0 : w - 1) * RS;
    float* rowAD = sA + (w == NW - 1 ? NW - 1 : w + 1) * RS;
    float* rowB  = sB + w * RS;
    float* rowBU = sB + (w == 0 ? 0 : w - 1) * RS;
    float* rowBD = sB + (w == NW - 1 ? NW - 1 : w + 1) * RS;

    const float  PINF = __int_as_float(0x7f800000);
    const float  NINF = __int_as_float(0xff800000);
    const float2 PI2  = make_float2(PINF, PINF);

    const long base = (long)b * Z * YX + (long)gy * X;
    const float* pIn = img + base + gx + (long)(z0 - 1) * YX;
    const float* pH  = img + base + hx + (long)(z0 - 1) * YX;
    float*       pO  = out + base + gx + (long)z0 * YX;

    // rings: v = img planes (zi-2, zi-1, zi); h = x-halo of same; e = erode planes
    float2 v0 = PI2, v1 = PI2, v2;
    float2 h0 = PI2, h1 = PI2, h2;
    float2 e0 = make_float2(NINF, NINF), e1 = e0;
    float  eS0 = NINF, eS1 = NINF;       // edge-erode ring (lanes 0/31)

    {   // preload plane z0-2
        const int zp = z0 - 2;
        const bool zok = (zp >= 0);      // zp < Z always here
        v2 = (rowV && zok) ? *(const float2*)(pIn - YX) : PI2;
        h2 = (rowV && zok && haloInX) ? *(const float2*)(pH - YX) : PI2;
    }

    for (int zi = z0 - 2; zi <= z1 + 1; ++zi) {
        // ---- prefetch plane zi+1 (overlaps this plane's compute)
        float2 vn = PI2, hn = PI2;
        {
            const int zn = zi + 1;
            const bool zok = ((unsigned)zn < Z);
            if (rowV && zok)            vn = *(const float2*)pIn;
            if (rowV && zok && haloInX) hn = *(const float2*)pH;
            pIn += YX; pH += YX;
        }

        // ---- erode-z at plane zc = zi-1 (registers)
        float2 zm = fmin2(v0, fmin2(v1, v2));
        float2 hz = fmin2(h0, fmin2(h1, h2));

        // ---- erode-x via shuffle
        float pv = __shfl_up_sync(0xffffffffu, zm.y, 1);
        float nx = __shfl_down_sync(0xffffffffu, zm.x, 1);
        if (isL) pv = hz.y;
        if (isR) nx = hz.x;
        float2 ex;
        ex.x = fminf(pv, fminf(zm.x, zm.y));
        ex.y = fminf(zm.x, fminf(zm.y, nx));
        float eSc = 0.0f;
        if (isE) {
            eSc = isR ? fminf(zm.y, fminf(hz.x, hz.y))
                      : fminf(fminf(hz.x, hz.y), zm.x);
        }

        // ---- erode-y via smem (buffer A)
        *(float2*)(rowA + 2 + 2 * lane) = ex;
        if (isE) rowA[ec] = eSc;
        __syncthreads();
        float2 uA = *(const float2*)(rowAU + 2 + 2 * lane);
        float2 dA = *(const float2*)(rowAD + 2 + 2 * lane);
        float2 ey = fmin2(uA, fmin2(ex, dA));

        // ---- domain mask (-inf outside image for dilate padding)
        const int  zc = zi - 1;
        const bool vC = rowV && ((unsigned)zc < Z);
        float2 en;
        en.x = vC ? ey.x : NINF;
        en.y = vC ? ey.y : NINF;

        float enE = NINF;
        if (isE) {
            float eyE = fminf(rowAU[ec], fminf(eSc, rowAD[ec]));
            enE = (vC && edgeInX) ? eyE : NINF;
        }

        // ---- dilate-z at plane zo = zi-2 (registers)
        float2 dd = fmax2(e0, fmax2(e1, en));
        float  dE = fmaxf(eS0, fmaxf(eS1, enE));
        e0 = e1; e1 = en; eS0 = eS1; eS1 = enE;

        // ---- dilate-x via shuffle
        float pvd = __shfl_up_sync(0xffffffffu, dd.y, 1);
        float nxd = __shfl_down_sync(0xffffffffu, dd.x, 1);
        if (isL) pvd = dE;
        if (isR) nxd = dE;
        float2 dx;
        dx.x = fmaxf(pvd, fmaxf(dd.x, dd.y));
        dx.y = fmaxf(dd.x, fmaxf(dd.y, nxd));

        // ---- dilate-y via smem (buffer B) + output
        *(float2*)(rowB + 2 + 2 * lane) = dx;
        __syncthreads();
        if (zi >= z0 + 2) {
            if (doOut) {
                float2 uB = *(const float2*)(rowBU + 2 + 2 * lane);
                float2 dB = *(const float2*)(rowBD + 2 + 2 * lane);
                float2 op = fmax2(uB, fmax2(dx, dB));
                float2 r;
                r.x = fmaxf(v0.x - op.x, 0.0f);   // v0 = img plane zo
                r.y = fmaxf(v0.y - op.y, 0.0f);
                *(float2*)pO = r;
            }
            pO += YX;
        }

        // ---- shift rings
        v0 = v1; v1 = v2; v2 = vn;
        h0 = h1; h1 = h2; h2 = hn;
    }
}

extern "C" void kernel_launch(void* const* d_in, const int* in_sizes, int n_in,
                              void* d_out, int out_size) {
    (void)in_sizes; (void)n_in; (void)out_size;
    const float* img = (const float*)d_in[0];
    float* out = (float*)d_out;
    dim3 grid(X / TX, Y / TY, NB * ZCHUNKS);
    soft_skel_kernel<<<grid, NTH>>>(img, out);
}